// round 2
// baseline (speedup 1.0000x reference)
#include <cuda_runtime.h>
#include <cuda_fp16.h>
#include <cstdint>

// ============================================================================
// FP8Linear: out[8192,4096] = scale * (x_f16 @ q_f16^T) + bias
//   q = fake-quant(weight) / scale  -> exactly representable in fp16
//   x rounded to fp16: rel err ~3e-4 over K=4096 dot products (gate: 1e-3)
// NOTE: harness ptxas targets plain sm_103 (no 'a') -> tcgen05/TMEM are
// unavailable. This uses base-ISA: cp.async.cg + ldmatrix + mma.sync (HMMA).
// ============================================================================
#define DIN   4096
#define DOUT  4096
#define MROWS 8192
#define E4M3_MAX 240.0f

// Scratch (allocation-guard-safe: __device__ globals)
__device__ __align__(1024) __half g_xh[(size_t)MROWS * DIN];   // 64 MB
__device__ __align__(1024) __half g_qw[(size_t)DOUT * DIN];    // 32 MB
__device__ unsigned int g_amax_bits;
__device__ float        g_scale;

// ============================================================================
// Preprocessing
// ============================================================================
__global__ void init_kernel() { g_amax_bits = 0u; }

__global__ void amax_kernel(const float* __restrict__ w, int n4) {
    const float4* w4 = (const float4*)w;
    float m = 0.0f;
    for (int i = blockIdx.x * blockDim.x + threadIdx.x; i < n4;
         i += gridDim.x * blockDim.x) {
        float4 v = w4[i];
        m = fmaxf(m, fmaxf(fmaxf(fabsf(v.x), fabsf(v.y)),
                           fmaxf(fabsf(v.z), fabsf(v.w))));
    }
    #pragma unroll
    for (int o = 16; o > 0; o >>= 1)
        m = fmaxf(m, __shfl_xor_sync(0xffffffffu, m, o));
    __shared__ float sm[32];
    int lane = threadIdx.x & 31, wid = threadIdx.x >> 5;
    if (lane == 0) sm[wid] = m;
    __syncthreads();
    if (wid == 0) {
        m = (lane < (int)(blockDim.x >> 5)) ? sm[lane] : 0.0f;
        #pragma unroll
        for (int o = 16; o > 0; o >>= 1)
            m = fmaxf(m, __shfl_xor_sync(0xffffffffu, m, o));
        if (lane == 0) atomicMax(&g_amax_bits, __float_as_uint(m));
    }
}

// q = clip(round(fp16(clip(w/scale,+-240)) * 8)/8, +-240); store fp16 (exact).
__global__ void quant_kernel(const float* __restrict__ w, int n4) {
    float amax  = __uint_as_float(g_amax_bits);
    float scale = fmaxf(amax / E4M3_MAX, 1e-10f);
    int i0 = blockIdx.x * blockDim.x + threadIdx.x;
    if (i0 == 0) g_scale = scale;
    const float4* w4 = (const float4*)w;
    __half2* dst = (__half2*)g_qw;
    for (int i = i0; i < n4; i += gridDim.x * blockDim.x) {
        float4 v = w4[i];
        float in[4] = {v.x, v.y, v.z, v.w};
        float q[4];
        #pragma unroll
        for (int j = 0; j < 4; j++) {
            float s = in[j] / scale;
            s = fminf(fmaxf(s, -E4M3_MAX), E4M3_MAX);
            s = __half2float(__float2half_rn(s));      // fp16 round-trip (RNE)
            float qq = rintf(s * 8.0f) * 0.125f;       // mantissa truncation
            q[j] = fminf(fmaxf(qq, -E4M3_MAX), E4M3_MAX);
        }
        dst[2 * i]     = __floats2half2_rn(q[0], q[1]);
        dst[2 * i + 1] = __floats2half2_rn(q[2], q[3]);
    }
}

__global__ void xconv_kernel(const float* __restrict__ x, int n4) {
    const float4* x4 = (const float4*)x;
    __half2* dst = (__half2*)g_xh;
    for (int i = blockIdx.x * blockDim.x + threadIdx.x; i < n4;
         i += gridDim.x * blockDim.x) {
        float4 v = x4[i];
        dst[2 * i]     = __floats2half2_rn(v.x, v.y);
        dst[2 * i + 1] = __floats2half2_rn(v.z, v.w);
    }
}

// ============================================================================
// GEMM: 128x128 CTA tile, BK=32, 4-stage cp.async, 8 warps (2x4), 64x32 warp
// tile, mma.sync.m16n8k16 f32.f16.f16. Smem rows padded to 40 halfs (80 B
// pitch) -> conflict-free ldmatrix phases.
// ============================================================================
static constexpr int BM = 128;
static constexpr int BN = 128;
static constexpr int BK = 32;
static constexpr int PITCH = BK + 8;             // 40 halfs = 80 B
static constexpr int TILE_HALFS = BM * PITCH;    // per operand per stage
static constexpr int NSTAGES = 4;
static constexpr int STAGE_HALFS = 2 * TILE_HALFS;
static constexpr int SMEM_BYTES = NSTAGES * STAGE_HALFS * 2;   // 81920
static constexpr int KT = DIN / BK;              // 128

__device__ __forceinline__ uint32_t smem_u32(const void* p) {
    uint32_t a;
    asm("{ .reg .u64 t; cvta.to.shared.u64 t, %1; cvt.u32.u64 %0, t; }"
        : "=r"(a) : "l"(p));
    return a;
}

__device__ __forceinline__ void cp16(uint32_t s, const void* g) {
    asm volatile("cp.async.cg.shared.global [%0], [%1], 16;"
                 :: "r"(s), "l"(g) : "memory");
}

__device__ __forceinline__ void ldm_x4(unsigned* r, uint32_t addr) {
    asm volatile("ldmatrix.sync.aligned.m8n8.x4.shared.b16 {%0,%1,%2,%3}, [%4];"
                 : "=r"(r[0]), "=r"(r[1]), "=r"(r[2]), "=r"(r[3]) : "r"(addr));
}

__device__ __forceinline__ void mma16816(float* d, const unsigned* a,
                                         unsigned b0, unsigned b1) {
    asm volatile(
        "mma.sync.aligned.m16n8k16.row.col.f32.f16.f16.f32 "
        "{%0,%1,%2,%3}, {%4,%5,%6,%7}, {%8,%9}, {%0,%1,%2,%3};"
        : "+f"(d[0]), "+f"(d[1]), "+f"(d[2]), "+f"(d[3])
        : "r"(a[0]), "r"(a[1]), "r"(a[2]), "r"(a[3]), "r"(b0), "r"(b1));
}

__device__ __forceinline__ void load_stage(uint32_t sA, uint32_t sB,
                                           int m0, int n0, int kt, int tid) {
    #pragma unroll
    for (int i = 0; i < 2; i++) {
        int cc  = tid + i * 256;
        int row = cc >> 2;
        int col = (cc & 3) * 8;                  // halfs
        cp16(sA + row * (PITCH * 2) + col * 2,
             g_xh + (size_t)(m0 + row) * DIN + kt * BK + col);
        cp16(sB + row * (PITCH * 2) + col * 2,
             g_qw + (size_t)(n0 + row) * DIN + kt * BK + col);
    }
}

__global__ __launch_bounds__(256, 2) void gemm_kernel(
    const float* __restrict__ bias, float* __restrict__ out)
{
    extern __shared__ __half smem[];
    const uint32_t sbase = smem_u32(smem);
    const int tid  = threadIdx.x;
    const int lane = tid & 31;
    const int wid  = tid >> 5;
    const int wm   = wid >> 2;                   // 0..1
    const int wn   = wid & 3;                    // 0..3
    const int m0   = blockIdx.y * BM;
    const int n0   = blockIdx.x * BN;

    float acc[4][4][4];
    #pragma unroll
    for (int i = 0; i < 4; i++)
        #pragma unroll
        for (int j = 0; j < 4; j++)
            #pragma unroll
            for (int k = 0; k < 4; k++) acc[i][j][k] = 0.0f;

    // Prologue: fill NSTAGES-1 stages
    #pragma unroll
    for (int s = 0; s < NSTAGES - 1; s++) {
        uint32_t sA = sbase + s * STAGE_HALFS * 2;
        uint32_t sB = sA + TILE_HALFS * 2;
        load_stage(sA, sB, m0, n0, s, tid);
        asm volatile("cp.async.commit_group;" ::: "memory");
    }

    // ldmatrix lane addressing (bytes, precomputed per-thread row parts)
    const int a_row = wm * 64 + (lane & 15);          // + mi*16
    const int a_col = ((lane >> 4) * 8);              // + kh*16, halfs
    const int b_row = wn * 32 + (lane & 7) + ((lane >> 4) & 1) * 8;  // + bj*16
    const int b_col = (((lane >> 3) & 1) * 8);        // + kh*16, halfs

    #pragma unroll 1
    for (int kt = 0; kt < KT; kt++) {
        asm volatile("cp.async.wait_group %0;" :: "n"(NSTAGES - 2) : "memory");
        __syncthreads();

        // Issue the next stage (slot freed by last iteration's compute)
        int ktn = kt + NSTAGES - 1;
        if (ktn < KT) {
            int s = ktn & (NSTAGES - 1);
            uint32_t sA = sbase + s * STAGE_HALFS * 2;
            uint32_t sB = sA + TILE_HALFS * 2;
            load_stage(sA, sB, m0, n0, ktn, tid);
        }
        asm volatile("cp.async.commit_group;" ::: "memory");

        const int st = kt & (NSTAGES - 1);
        const uint32_t sA = sbase + st * STAGE_HALFS * 2;
        const uint32_t sB = sA + TILE_HALFS * 2;

        #pragma unroll
        for (int kh = 0; kh < 2; kh++) {
            unsigned a[4][4], b[2][4];
            #pragma unroll
            for (int mi = 0; mi < 4; mi++)
                ldm_x4(a[mi], sA + (a_row + mi * 16) * (PITCH * 2)
                                 + (a_col + kh * 16) * 2);
            #pragma unroll
            for (int bj = 0; bj < 2; bj++)
                ldm_x4(b[bj], sB + (b_row + bj * 16) * (PITCH * 2)
                                 + (b_col + kh * 16) * 2);
            #pragma unroll
            for (int mi = 0; mi < 4; mi++)
                #pragma unroll
                for (int nj = 0; nj < 4; nj++)
                    mma16816(acc[mi][nj], a[mi],
                             b[nj >> 1][(nj & 1) * 2],
                             b[nj >> 1][(nj & 1) * 2 + 1]);
        }
        __syncthreads();
    }

    // Epilogue: out = scale*acc + bias
    const float scale = g_scale;
    const int rq = lane >> 2;                    // 0..7
    const int cq = (lane & 3) * 2;               // 0,2,4,6
    #pragma unroll
    for (int mi = 0; mi < 4; mi++) {
        #pragma unroll
        for (int nj = 0; nj < 4; nj++) {
            int row = m0 + wm * 64 + mi * 16 + rq;
            int col = n0 + wn * 32 + nj * 8 + cq;
            float2 bv = *(const float2*)(bias + col);
            float2 v0, v1;
            v0.x = fmaf(scale, acc[mi][nj][0], bv.x);
            v0.y = fmaf(scale, acc[mi][nj][1], bv.y);
            v1.x = fmaf(scale, acc[mi][nj][2], bv.x);
            v1.y = fmaf(scale, acc[mi][nj][3], bv.y);
            *(float2*)(out + (size_t)row * DOUT + col) = v0;
            *(float2*)(out + (size_t)(row + 8) * DOUT + col) = v1;
        }
    }
}

// ============================================================================
// Host launch
// ============================================================================
extern "C" void kernel_launch(void* const* d_in, const int* in_sizes, int n_in,
                              void* d_out, int out_size) {
    const float* x    = (const float*)d_in[0];   // [8192, 4096]
    const float* w    = (const float*)d_in[1];   // [4096, 4096]
    const float* bias = (const float*)d_in[2];   // [4096]
    float* out = (float*)d_out;

    init_kernel<<<1, 1>>>();
    amax_kernel<<<1024, 256>>>(w, DOUT * DIN / 4);
    quant_kernel<<<2048, 256>>>(w, DOUT * DIN / 4);
    xconv_kernel<<<4096, 256>>>(x, MROWS * DIN / 4);

    static bool attr_set = false;
    if (!attr_set) {
        cudaFuncSetAttribute(gemm_kernel,
                             cudaFuncAttributeMaxDynamicSharedMemorySize,
                             SMEM_BYTES);
        attr_set = true;
    }
    dim3 grid(DOUT / BN, MROWS / BM);            // (32, 64)
    gemm_kernel<<<grid, 256, SMEM_BYTES>>>(bias, out);
}

// round 3
// speedup vs baseline: 1.1556x; 1.1556x over previous
#include <cuda_runtime.h>
#include <cuda_fp16.h>
#include <cstdint>

// ============================================================================
// FP8Linear: out[8192,4096] = scale * (x_f16 @ q_f16^T) + bias
//   q = fake-quant(weight)/scale -> exactly representable in fp16 (k/8 grid)
//   x rounded to fp16: dot-product rel err ~2e-4 (gate 1e-3) -- validated R2.
// Plain-sm_103 ptxas (no 'a') => tcgen05 unavailable; base-ISA HMMA path:
// cp.async.cg + ldmatrix + mma.sync.m16n8k16.
// R3: BK 32->64, 3-stage ring, ONE __syncthreads per mainloop iteration.
// ============================================================================
#define DIN   4096
#define DOUT  4096
#define MROWS 8192
#define E4M3_MAX 240.0f

__device__ __align__(1024) __half g_xh[(size_t)MROWS * DIN];   // 64 MB
__device__ __align__(1024) __half g_qw[(size_t)DOUT * DIN];    // 32 MB
__device__ unsigned int g_amax_bits;
__device__ float        g_scale;

// ============================================================================
// Preprocessing
// ============================================================================
__global__ void amax_kernel(const float* __restrict__ w, int n4) {
    const float4* w4 = (const float4*)w;
    float m = 0.0f;
    for (int i = blockIdx.x * blockDim.x + threadIdx.x; i < n4;
         i += gridDim.x * blockDim.x) {
        float4 v = w4[i];
        m = fmaxf(m, fmaxf(fmaxf(fabsf(v.x), fabsf(v.y)),
                           fmaxf(fabsf(v.z), fabsf(v.w))));
    }
    #pragma unroll
    for (int o = 16; o > 0; o >>= 1)
        m = fmaxf(m, __shfl_xor_sync(0xffffffffu, m, o));
    __shared__ float sm[32];
    int lane = threadIdx.x & 31, wid = threadIdx.x >> 5;
    if (lane == 0) sm[wid] = m;
    __syncthreads();
    if (wid == 0) {
        m = (lane < (int)(blockDim.x >> 5)) ? sm[lane] : 0.0f;
        #pragma unroll
        for (int o = 16; o > 0; o >>= 1)
            m = fmaxf(m, __shfl_xor_sync(0xffffffffu, m, o));
        if (lane == 0) atomicMax(&g_amax_bits, __float_as_uint(m));
    }
}

// q = clip(round(fp16(clip(w/scale,+-240)) * 8)/8, +-240); store fp16 (exact).
__global__ void quant_kernel(const float* __restrict__ w, int n4) {
    float amax  = __uint_as_float(g_amax_bits);
    float scale = fmaxf(amax / E4M3_MAX, 1e-10f);
    int i0 = blockIdx.x * blockDim.x + threadIdx.x;
    if (i0 == 0) g_scale = scale;
    const float4* w4 = (const float4*)w;
    __half2* dst = (__half2*)g_qw;
    for (int i = i0; i < n4; i += gridDim.x * blockDim.x) {
        float4 v = w4[i];
        float in[4] = {v.x, v.y, v.z, v.w};
        float q[4];
        #pragma unroll
        for (int j = 0; j < 4; j++) {
            float s = in[j] / scale;
            s = fminf(fmaxf(s, -E4M3_MAX), E4M3_MAX);
            s = __half2float(__float2half_rn(s));      // fp16 round-trip (RNE)
            float qq = rintf(s * 8.0f) * 0.125f;       // mantissa truncation
            q[j] = fminf(fmaxf(qq, -E4M3_MAX), E4M3_MAX);
        }
        dst[2 * i]     = __floats2half2_rn(q[0], q[1]);
        dst[2 * i + 1] = __floats2half2_rn(q[2], q[3]);
    }
}

__global__ void xconv_kernel(const float* __restrict__ x, int n4) {
    const float4* x4 = (const float4*)x;
    __half2* dst = (__half2*)g_xh;
    for (int i = blockIdx.x * blockDim.x + threadIdx.x; i < n4;
         i += gridDim.x * blockDim.x) {
        float4 v = x4[i];
        dst[2 * i]     = __floats2half2_rn(v.x, v.y);
        dst[2 * i + 1] = __floats2half2_rn(v.z, v.w);
    }
}

// ============================================================================
// GEMM: 128x128 CTA tile, BK=64, 3-stage cp.async ring, 8 warps (2x4),
// 64x32 warp tile, mma.sync.m16n8k16. PITCH=72 halfs -> conflict-free LDSM.
// ============================================================================
static constexpr int BM = 128;
static constexpr int BN = 128;
static constexpr int BK = 64;
static constexpr int PITCH = BK + 8;               // 72 halfs = 144 B
static constexpr int TILE_HALFS = BM * PITCH;      // 9216 per operand/stage
static constexpr int NSTAGES = 3;
static constexpr int STAGE_HALFS = 2 * TILE_HALFS;
static constexpr int STAGE_BYTES = STAGE_HALFS * 2;           // 36864
static constexpr int SMEM_BYTES = NSTAGES * STAGE_BYTES;      // 110592
static constexpr int KT = DIN / BK;                // 64

__device__ __forceinline__ uint32_t smem_u32(const void* p) {
    uint32_t a;
    asm("{ .reg .u64 t; cvta.to.shared.u64 t, %1; cvt.u32.u64 %0, t; }"
        : "=r"(a) : "l"(p));
    return a;
}

__device__ __forceinline__ void cp16(uint32_t s, const void* g) {
    asm volatile("cp.async.cg.shared.global [%0], [%1], 16;"
                 :: "r"(s), "l"(g) : "memory");
}

__device__ __forceinline__ void ldm_x4(unsigned* r, uint32_t addr) {
    asm volatile("ldmatrix.sync.aligned.m8n8.x4.shared.b16 {%0,%1,%2,%3}, [%4];"
                 : "=r"(r[0]), "=r"(r[1]), "=r"(r[2]), "=r"(r[3]) : "r"(addr));
}

__device__ __forceinline__ void mma16816(float* d, const unsigned* a,
                                         unsigned b0, unsigned b1) {
    asm volatile(
        "mma.sync.aligned.m16n8k16.row.col.f32.f16.f16.f32 "
        "{%0,%1,%2,%3}, {%4,%5,%6,%7}, {%8,%9}, {%0,%1,%2,%3};"
        : "+f"(d[0]), "+f"(d[1]), "+f"(d[2]), "+f"(d[3])
        : "r"(a[0]), "r"(a[1]), "r"(a[2]), "r"(a[3]), "r"(b0), "r"(b1));
}

// Fill one stage: 128 rows x 64 halfs per operand = 1024 16B-chunks each;
// 256 threads -> 4 chunks per thread per operand.
__device__ __forceinline__ void load_stage(uint32_t sA, uint32_t sB,
                                           int m0, int n0, int kt, int tid) {
    #pragma unroll
    for (int i = 0; i < 4; i++) {
        int cc  = tid + i * 256;
        int row = cc >> 3;
        int col = (cc & 7) * 8;                    // halfs
        cp16(sA + row * (PITCH * 2) + col * 2,
             g_xh + (size_t)(m0 + row) * DIN + kt * BK + col);
        cp16(sB + row * (PITCH * 2) + col * 2,
             g_qw + (size_t)(n0 + row) * DIN + kt * BK + col);
    }
}

__global__ __launch_bounds__(256, 2) void gemm_kernel(
    const float* __restrict__ bias, float* __restrict__ out)
{
    extern __shared__ __half smem[];
    const uint32_t sbase = smem_u32(smem);
    const int tid  = threadIdx.x;
    const int lane = tid & 31;
    const int wid  = tid >> 5;
    const int wm   = wid >> 2;                     // 0..1
    const int wn   = wid & 3;                      // 0..3
    const int m0   = blockIdx.y * BM;
    const int n0   = blockIdx.x * BN;

    float acc[4][4][4];
    #pragma unroll
    for (int i = 0; i < 4; i++)
        #pragma unroll
        for (int j = 0; j < 4; j++)
            #pragma unroll
            for (int k = 0; k < 4; k++) acc[i][j][k] = 0.0f;

    // Prologue: fill stages 0,1
    #pragma unroll
    for (int s = 0; s < NSTAGES - 1; s++) {
        uint32_t sA = sbase + s * STAGE_BYTES;
        load_stage(sA, sA + TILE_HALFS * 2, m0, n0, s, tid);
        asm volatile("cp.async.commit_group;" ::: "memory");
    }

    // ldmatrix lane addressing (rows in halfs-pitch units)
    const int a_row = wm * 64 + (lane & 15);                         // + mi*16
    const int a_col = ((lane >> 4) * 8);                             // + kh*16
    const int b_row = wn * 32 + (lane & 7) + ((lane >> 4) & 1) * 8;  // + bj*16
    const int b_col = (((lane >> 3) & 1) * 8);                       // + kh*16

    int st_c = 0;             // compute slot
    int st_l = NSTAGES - 1;   // load slot
    #pragma unroll 1
    for (int kt = 0; kt < KT; kt++) {
        // Oldest pending group (stage kt) complete:
        asm volatile("cp.async.wait_group %0;" :: "n"(NSTAGES - 2) : "memory");
        __syncthreads();   // also closes last iter's reads of slot st_l

        int ktn = kt + NSTAGES - 1;
        if (ktn < KT) {
            uint32_t sA = sbase + st_l * STAGE_BYTES;
            load_stage(sA, sA + TILE_HALFS * 2, m0, n0, ktn, tid);
        }
        asm volatile("cp.async.commit_group;" ::: "memory");

        const uint32_t sA = sbase + st_c * STAGE_BYTES;
        const uint32_t sB = sA + TILE_HALFS * 2;

        #pragma unroll
        for (int kh = 0; kh < BK / 16; kh++) {
            unsigned a[4][4], b[2][4];
            #pragma unroll
            for (int mi = 0; mi < 4; mi++)
                ldm_x4(a[mi], sA + (a_row + mi * 16) * (PITCH * 2)
                                 + (a_col + kh * 16) * 2);
            #pragma unroll
            for (int bj = 0; bj < 2; bj++)
                ldm_x4(b[bj], sB + (b_row + bj * 16) * (PITCH * 2)
                                 + (b_col + kh * 16) * 2);
            #pragma unroll
            for (int mi = 0; mi < 4; mi++)
                #pragma unroll
                for (int nj = 0; nj < 4; nj++)
                    mma16816(acc[mi][nj], a[mi],
                             b[nj >> 1][(nj & 1) * 2],
                             b[nj >> 1][(nj & 1) * 2 + 1]);
        }

        st_c = (st_c + 1 == NSTAGES) ? 0 : st_c + 1;
        st_l = (st_l + 1 == NSTAGES) ? 0 : st_l + 1;
    }

    // Epilogue: out = scale*acc + bias
    const float scale = g_scale;
    const int rq = lane >> 2;
    const int cq = (lane & 3) * 2;
    #pragma unroll
    for (int mi = 0; mi < 4; mi++) {
        #pragma unroll
        for (int nj = 0; nj < 4; nj++) {
            int row = m0 + wm * 64 + mi * 16 + rq;
            int col = n0 + wn * 32 + nj * 8 + cq;
            float2 bv = *(const float2*)(bias + col);
            float2 v0, v1;
            v0.x = fmaf(scale, acc[mi][nj][0], bv.x);
            v0.y = fmaf(scale, acc[mi][nj][1], bv.y);
            v1.x = fmaf(scale, acc[mi][nj][2], bv.x);
            v1.y = fmaf(scale, acc[mi][nj][3], bv.y);
            *(float2*)(out + (size_t)row * DOUT + col) = v0;
            *(float2*)(out + (size_t)(row + 8) * DOUT + col) = v1;
        }
    }
}

// ============================================================================
// Host launch
// ============================================================================
extern "C" void kernel_launch(void* const* d_in, const int* in_sizes, int n_in,
                              void* d_out, int out_size) {
    const float* x    = (const float*)d_in[0];   // [8192, 4096]
    const float* w    = (const float*)d_in[1];   // [4096, 4096]
    const float* bias = (const float*)d_in[2];   // [4096]
    float* out = (float*)d_out;

    void* amax_ptr = nullptr;
    cudaGetSymbolAddress(&amax_ptr, g_amax_bits);
    cudaMemsetAsync(amax_ptr, 0, sizeof(unsigned int));

    amax_kernel<<<1024, 256>>>(w, DOUT * DIN / 4);
    quant_kernel<<<2048, 256>>>(w, DOUT * DIN / 4);
    xconv_kernel<<<4096, 256>>>(x, MROWS * DIN / 4);

    cudaFuncSetAttribute(gemm_kernel,
                         cudaFuncAttributeMaxDynamicSharedMemorySize,
                         SMEM_BYTES);
    dim3 grid(DOUT / BN, MROWS / BM);            // (32, 64)
    gemm_kernel<<<grid, 256, SMEM_BYTES>>>(bias, out);
}

// round 5
// speedup vs baseline: 1.5501x; 1.3414x over previous
#include <cuda_runtime.h>
#include <cuda_fp16.h>
#include <cstdint>

// ============================================================================
// FP8Linear: out[8192,4096] = scale * (x_f16 @ q_f16^T) + bias
//   q = fake-quant(weight)/scale -> exact in fp16; x->fp16 gives rel_err 2e-4.
// Plain-sm_103 ptxas => no tcgen05. HMMA path: cp.async + ldmatrix + mma.sync.
// R4/R5: CTA 128x256, warp 64x64, 3-stage, register-double-buffered fragments,
// CUTLASS-multistage ordering (wait+sync inside kh loop, overlapped by MMAs).
// (Resubmission of R4 — prior round died on broker timeout, kernel untested.)
// ============================================================================
#define DIN   4096
#define DOUT  4096
#define MROWS 8192
#define E4M3_MAX 240.0f

__device__ __align__(1024) __half g_xh[(size_t)MROWS * DIN];   // 64 MB
__device__ __align__(1024) __half g_qw[(size_t)DOUT * DIN];    // 32 MB
__device__ unsigned int g_amax_bits;
__device__ float        g_scale;

// ============================================================================
// Preprocessing
// ============================================================================
__global__ void amax_kernel(const float* __restrict__ w, int n4) {
    const float4* w4 = (const float4*)w;
    float m = 0.0f;
    for (int i = blockIdx.x * blockDim.x + threadIdx.x; i < n4;
         i += gridDim.x * blockDim.x) {
        float4 v = w4[i];
        m = fmaxf(m, fmaxf(fmaxf(fabsf(v.x), fabsf(v.y)),
                           fmaxf(fabsf(v.z), fabsf(v.w))));
    }
    #pragma unroll
    for (int o = 16; o > 0; o >>= 1)
        m = fmaxf(m, __shfl_xor_sync(0xffffffffu, m, o));
    __shared__ float sm[32];
    int lane = threadIdx.x & 31, wid = threadIdx.x >> 5;
    if (lane == 0) sm[wid] = m;
    __syncthreads();
    if (wid == 0) {
        m = (lane < (int)(blockDim.x >> 5)) ? sm[lane] : 0.0f;
        #pragma unroll
        for (int o = 16; o > 0; o >>= 1)
            m = fmaxf(m, __shfl_xor_sync(0xffffffffu, m, o));
        if (lane == 0) atomicMax(&g_amax_bits, __float_as_uint(m));
    }
}

__global__ void quant_kernel(const float* __restrict__ w, int n4) {
    float amax  = __uint_as_float(g_amax_bits);
    float scale = fmaxf(amax / E4M3_MAX, 1e-10f);
    int i0 = blockIdx.x * blockDim.x + threadIdx.x;
    if (i0 == 0) g_scale = scale;
    const float4* w4 = (const float4*)w;
    __half2* dst = (__half2*)g_qw;
    for (int i = i0; i < n4; i += gridDim.x * blockDim.x) {
        float4 v = w4[i];
        float in[4] = {v.x, v.y, v.z, v.w};
        float q[4];
        #pragma unroll
        for (int j = 0; j < 4; j++) {
            float s = in[j] / scale;
            s = fminf(fmaxf(s, -E4M3_MAX), E4M3_MAX);
            s = __half2float(__float2half_rn(s));
            float qq = rintf(s * 8.0f) * 0.125f;
            q[j] = fminf(fmaxf(qq, -E4M3_MAX), E4M3_MAX);
        }
        dst[2 * i]     = __floats2half2_rn(q[0], q[1]);
        dst[2 * i + 1] = __floats2half2_rn(q[2], q[3]);
    }
}

__global__ void xconv_kernel(const float* __restrict__ x, int n4) {
    const float4* x4 = (const float4*)x;
    __half2* dst = (__half2*)g_xh;
    for (int i = blockIdx.x * blockDim.x + threadIdx.x; i < n4;
         i += gridDim.x * blockDim.x) {
        float4 v = x4[i];
        dst[2 * i]     = __floats2half2_rn(v.x, v.y);
        dst[2 * i + 1] = __floats2half2_rn(v.z, v.w);
    }
}

// ============================================================================
// GEMM: CTA 128(M) x 256(N), BK=64, 3 stages, 8 warps (wm 0..1 x wn 0..3),
// warp tile 64x64, register-double-buffered fragments.
// ============================================================================
static constexpr int BM = 128;
static constexpr int BN = 256;
static constexpr int BK = 64;
static constexpr int PITCH = BK + 8;                   // 72 halfs = 144 B
static constexpr int A_HALFS = BM * PITCH;             // 9216
static constexpr int B_HALFS = BN * PITCH;             // 18432
static constexpr int NSTAGES = 3;
static constexpr int STAGE_BYTES = (A_HALFS + B_HALFS) * 2;   // 55296
static constexpr int SMEM_BYTES = NSTAGES * STAGE_BYTES;      // 165888
static constexpr int KT = DIN / BK;                    // 64
static constexpr int KH = BK / 16;                     // 4

__device__ __forceinline__ uint32_t smem_u32(const void* p) {
    uint32_t a;
    asm("{ .reg .u64 t; cvta.to.shared.u64 t, %1; cvt.u32.u64 %0, t; }"
        : "=r"(a) : "l"(p));
    return a;
}
__device__ __forceinline__ void cp16(uint32_t s, const void* g) {
    asm volatile("cp.async.cg.shared.global [%0], [%1], 16;"
                 :: "r"(s), "l"(g) : "memory");
}
__device__ __forceinline__ void ldm_x4(unsigned* r, uint32_t addr) {
    asm volatile("ldmatrix.sync.aligned.m8n8.x4.shared.b16 {%0,%1,%2,%3}, [%4];"
                 : "=r"(r[0]), "=r"(r[1]), "=r"(r[2]), "=r"(r[3]) : "r"(addr));
}
__device__ __forceinline__ void mma16816(float* d, const unsigned* a,
                                         unsigned b0, unsigned b1) {
    asm volatile(
        "mma.sync.aligned.m16n8k16.row.col.f32.f16.f16.f32 "
        "{%0,%1,%2,%3}, {%4,%5,%6,%7}, {%8,%9}, {%0,%1,%2,%3};"
        : "+f"(d[0]), "+f"(d[1]), "+f"(d[2]), "+f"(d[3])
        : "r"(a[0]), "r"(a[1]), "r"(a[2]), "r"(a[3]), "r"(b0), "r"(b1));
}

// Fill one stage: A 1024 chunks (4/thread), B 2048 chunks (8/thread).
__device__ __forceinline__ void load_stage(uint32_t sA, int m0, int n0,
                                           int kt, int tid) {
    uint32_t sB = sA + A_HALFS * 2;
    const __half* gA = g_xh + (size_t)m0 * DIN + kt * BK;
    const __half* gB = g_qw + (size_t)n0 * DIN + kt * BK;
    #pragma unroll
    for (int i = 0; i < 4; i++) {
        int cc = tid + i * 256, row = cc >> 3, col = (cc & 7) * 8;
        cp16(sA + row * (PITCH * 2) + col * 2, gA + (size_t)row * DIN + col);
    }
    #pragma unroll
    for (int i = 0; i < 8; i++) {
        int cc = tid + i * 256, row = cc >> 3, col = (cc & 7) * 8;
        cp16(sB + row * (PITCH * 2) + col * 2, gB + (size_t)row * DIN + col);
    }
}

__global__ __launch_bounds__(256, 1) void gemm_kernel(
    const float* __restrict__ bias, float* __restrict__ out)
{
    extern __shared__ __half smem[];
    const uint32_t sbase = smem_u32(smem);
    const int tid  = threadIdx.x;
    const int lane = tid & 31;
    const int wid  = tid >> 5;
    const int wm   = wid >> 2;                     // 0..1 (M)
    const int wn   = wid & 3;                      // 0..3 (N)
    const int m0   = blockIdx.y * BM;
    const int n0   = blockIdx.x * BN;

    float acc[4][8][4];
    #pragma unroll
    for (int i = 0; i < 4; i++)
        #pragma unroll
        for (int j = 0; j < 8; j++)
            #pragma unroll
            for (int k = 0; k < 4; k++) acc[i][j][k] = 0.0f;

    // Per-thread intra-stage ldmatrix byte offsets
    const int a_row = wm * 64 + (lane & 15);
    const int a_col = (lane >> 4) * 8;                              // halfs
    const int b_row = wn * 64 + (lane & 7) + ((lane >> 4) & 1) * 8;
    const int b_col = ((lane >> 3) & 1) * 8;                        // halfs
    uint32_t a_off[4], b_off[4];
    #pragma unroll
    for (int mi = 0; mi < 4; mi++)
        a_off[mi] = (uint32_t)((a_row + mi * 16) * (PITCH * 2) + a_col * 2);
    #pragma unroll
    for (int bj = 0; bj < 4; bj++)
        b_off[bj] = (uint32_t)(A_HALFS * 2
                    + (b_row + bj * 16) * (PITCH * 2) + b_col * 2);

    // Prologue: stages 0,1
    #pragma unroll
    for (int s = 0; s < NSTAGES - 1; s++) {
        load_stage(sbase + s * STAGE_BYTES, m0, n0, s, tid);
        asm volatile("cp.async.commit_group;" ::: "memory");
    }
    asm volatile("cp.async.wait_group 1;" ::: "memory");
    __syncthreads();

    unsigned fa[2][4][4], fb[2][4][4];
    uint32_t rd = sbase;                  // read-stage base
    int rd_i = 0, wr_i = NSTAGES - 1;

    // Load kh=0 fragments into buffer 0
    #pragma unroll
    for (int mi = 0; mi < 4; mi++) ldm_x4(fa[0][mi], rd + a_off[mi]);
    #pragma unroll
    for (int bj = 0; bj < 4; bj++) ldm_x4(fb[0][bj], rd + b_off[bj]);

    #pragma unroll 1
    for (int kt = 0; kt < KT; kt++) {
        #pragma unroll
        for (int kh = 0; kh < KH; kh++) {
            if (kh == KH - 1) {
                asm volatile("cp.async.wait_group 1;" ::: "memory");
                __syncthreads();
                rd_i = (rd_i + 1 == NSTAGES) ? 0 : rd_i + 1;
                rd = sbase + rd_i * STAGE_BYTES;
            }
            // Prefetch next slice's fragments (next stage's kh=0 at boundary)
            const int nkh = (kh + 1) & (KH - 1);
            const int nbuf = (kh + 1) & 1;
            const uint32_t koff = (uint32_t)(nkh * 16 * 2);  // halfs->bytes
            #pragma unroll
            for (int mi = 0; mi < 4; mi++)
                ldm_x4(fa[nbuf][mi], rd + a_off[mi] + koff);
            #pragma unroll
            for (int bj = 0; bj < 4; bj++)
                ldm_x4(fb[nbuf][bj], rd + b_off[bj] + koff);

            if (kh == 0) {
                if (kt + 2 < KT)
                    load_stage(sbase + wr_i * STAGE_BYTES, m0, n0, kt + 2, tid);
                asm volatile("cp.async.commit_group;" ::: "memory");
                wr_i = (wr_i + 1 == NSTAGES) ? 0 : wr_i + 1;
            }

            const int cbuf = kh & 1;
            #pragma unroll
            for (int mi = 0; mi < 4; mi++)
                #pragma unroll
                for (int nj = 0; nj < 8; nj++)
                    mma16816(acc[mi][nj], fa[cbuf][mi],
                             fb[cbuf][nj >> 1][(nj & 1) * 2],
                             fb[cbuf][nj >> 1][(nj & 1) * 2 + 1]);
        }
    }

    // Epilogue: out = scale*acc + bias
    const float scale = g_scale;
    const int rq = lane >> 2;
    const int cq = (lane & 3) * 2;
    #pragma unroll
    for (int mi = 0; mi < 4; mi++) {
        #pragma unroll
        for (int nj = 0; nj < 8; nj++) {
            int row = m0 + wm * 64 + mi * 16 + rq;
            int col = n0 + wn * 64 + nj * 8 + cq;
            float2 bv = *(const float2*)(bias + col);
            float2 v0, v1;
            v0.x = fmaf(scale, acc[mi][nj][0], bv.x);
            v0.y = fmaf(scale, acc[mi][nj][1], bv.y);
            v1.x = fmaf(scale, acc[mi][nj][2], bv.x);
            v1.y = fmaf(scale, acc[mi][nj][3], bv.y);
            *(float2*)(out + (size_t)row * DOUT + col) = v0;
            *(float2*)(out + (size_t)(row + 8) * DOUT + col) = v1;
        }
    }
}

// ============================================================================
// Host launch
// ============================================================================
extern "C" void kernel_launch(void* const* d_in, const int* in_sizes, int n_in,
                              void* d_out, int out_size) {
    const float* x    = (const float*)d_in[0];
    const float* w    = (const float*)d_in[1];
    const float* bias = (const float*)d_in[2];
    float* out = (float*)d_out;

    void* amax_ptr = nullptr;
    cudaGetSymbolAddress(&amax_ptr, g_amax_bits);
    cudaMemsetAsync(amax_ptr, 0, sizeof(unsigned int));

    amax_kernel<<<1024, 256>>>(w, DOUT * DIN / 4);
    quant_kernel<<<2048, 256>>>(w, DOUT * DIN / 4);
    xconv_kernel<<<4096, 256>>>(x, MROWS * DIN / 4);

    cudaFuncSetAttribute(gemm_kernel,
                         cudaFuncAttributeMaxDynamicSharedMemorySize,
                         SMEM_BYTES);
    dim3 grid(DOUT / BN, MROWS / BM);              // (16, 64) = 1024 CTAs
    gemm_kernel<<<grid, 256, SMEM_BYTES>>>(bias, out);
}